// round 14
// baseline (speedup 1.0000x reference)
#include <cuda_runtime.h>
#include <cuda_bf16.h>

#define N_GRAPHS 64
#define DIMTOT   240     // 64*1 + 32*3 + 16*5
#define NF2      120     // DIMTOT/2
#define NFLOAT4  60      // DIMTOT/4
#define EPS      1e-05f
#define STATS_GRID 1536  // blocks; each owns ~130 contiguous nodes

// stats layout per graph: [0]=count, [1]=s0, [2]=ss0, [3..5]=s1[d], [6..10]=s2[d]
__device__ float g_stats[N_GRAPHS][12];   // zero at load; re-zeroed by apply epilogue
__device__ float g_A[N_GRAPHS * DIMTOT];
__device__ float g_B[N_GRAPHS * DIMTOT];

__device__ __forceinline__ int bucket_of(int c) {   // -> index into g_stats row minus 1 (0..9)
    if (c < 64) return 0;
    if (c < 160) return 2 + (c - 64) % 3;
    return 5 + (c - 160) % 5;
}

// ---------------------------------------------------------------------------
// Pass 1 (column-striped, float2 lanes): block b owns nodes [bN/B,(b+1)N/B).
// Warp w: column-warp cw=w%4 covers float2 indices [32cw,32cw+32) (cw=3: 24
// lanes), parity p=w/4 covers nodes first=n0+p step 2. Each lane: ONE float2
// (2 adjacent cols), fixed buckets, no routing in hot loop. Class boundaries
// (64,160) are even -> no float2 straddles classes; cw==0 is uniformly l=0.
// 8-load chunks (2KB outstanding/warp) with single batch check per chunk.
// ---------------------------------------------------------------------------
__global__ __launch_bounds__(256) void stats_kernel(const float* __restrict__ x,
                                                    const int* __restrict__ batch,
                                                    int n_nodes) {
    const int b = blockIdx.x;
    const int warp = threadIdx.x >> 5;
    const int lane = threadIdx.x & 31;
    const int cw = warp & 3;
    const int p = warp >> 2;
    const int n0 = (int)((long long)b * n_nodes / STATS_GRID);
    const int n1 = (int)((long long)(b + 1) * n_nodes / STATS_GRID);
    const int first = n0 + p;
    if (first >= n1) return;

    const int m = cw * 32 + lane;           // float2 index
    const bool active = (m < NF2);
    const bool isA = (cw == 0);             // cols 0..63: l=0 class (warp-uniform)
    const int b0 = active ? bucket_of(2 * m) : 0;
    const int b1 = active ? bucket_of(2 * m + 1) : 0;

    float2 acc = make_float2(0.f, 0.f);
    float2 asq = make_float2(0.f, 0.f);

    auto flush = [&](int g, int cntv) {
        float v[10];
#pragma unroll
        for (int i = 0; i < 10; i++) {
            float s = 0.f;
            if (active && b0 == i) s += acc.x;
            if (active && b1 == i) s += acc.y;
            v[i] = s;
        }
        if (isA) v[1] += asq.x + asq.y;
#pragma unroll
        for (int off = 16; off > 0; off >>= 1) {
#pragma unroll
            for (int i = 0; i < 10; i++)
                v[i] += __shfl_xor_sync(0xFFFFFFFFu, v[i], off);
        }
        if (lane == 0) {
#pragma unroll
            for (int i = 0; i < 10; i++)
                atomicAdd(&g_stats[g][1 + i], v[i]);
            if (cw == 0) atomicAdd(&g_stats[g][0], (float)cntv);
        }
    };

    const int gfirst = __ldg(&batch[n0]);
    const int glast = __ldg(&batch[n1 - 1]);
    const float2* p2 = (const float2*)x + (size_t)first * NF2 + m;

    if (gfirst == glast) {
        // ---- fast path: whole block range in one graph (~96% of blocks) ----
        int n = first;
        for (; n + 14 < n1; n += 16, p2 += 16 * NF2) {
            float2 t[8];
#pragma unroll
            for (int u = 0; u < 8; u++)
                t[u] = active ? __ldg(p2 + u * (2 * NF2)) : make_float2(0.f, 0.f);
#pragma unroll
            for (int u = 0; u < 8; u++) {
                acc.x += t[u].x;
                acc.y += t[u].y;
                if (isA) {
                    asq.x += t[u].x * t[u].x;
                    asq.y += t[u].y * t[u].y;
                }
            }
        }
        for (; n < n1; n += 2, p2 += 2 * NF2) {
            float2 v = active ? __ldg(p2) : make_float2(0.f, 0.f);
            acc.x += v.x;
            acc.y += v.y;
            if (isA) {
                asq.x += v.x * v.x;
                asq.y += v.y * v.y;
            }
        }
        flush(gfirst, (n1 - first + 1) >> 1);
    } else {
        // ---- slow path: graph boundary inside block range (rare) ----
        int cur_g = __ldg(&batch[first]);
        int cnt = 0;
        for (int n = first; n < n1; n += 2, p2 += 2 * NF2) {
            int g = __ldg(&batch[n]);
            if (g != cur_g) {
                flush(cur_g, cnt);
                cur_g = g;
                cnt = 0;
                acc = make_float2(0.f, 0.f);
                asq = make_float2(0.f, 0.f);
            }
            float2 v = active ? __ldg(p2) : make_float2(0.f, 0.f);
            acc.x += v.x;
            acc.y += v.y;
            if (isA) {
                asq.x += v.x * v.x;
                asq.y += v.y * v.y;
            }
            cnt++;
        }
        flush(cur_g, cnt);
    }
}

// ---------------------------------------------------------------------------
// Pass 1.5: build per-(graph,column) affine params  out = x*A + B
// ---------------------------------------------------------------------------
__global__ void params_kernel(const float* __restrict__ weight,
                              const float* __restrict__ bias) {
    int idx = blockIdx.x * blockDim.x + threadIdx.x;
    if (idx >= N_GRAPHS * DIMTOT) return;
    int g = idx / DIMTOT;
    int c = idx - g * DIMTOT;

    float cntf = fmaxf(g_stats[g][0], 1.0f);
    float a, b;
    if (c < 64) {
        float inv64 = 1.0f / (cntf * 64.0f);
        float m = g_stats[g][1] * inv64;
        float var = g_stats[g][2] * inv64 - m * m;
        float inv = 1.0f / (sqrtf(fmaxf(var, 0.0f)) + EPS);
        a = weight[c] * inv;
        b = bias[c] - m * a;
    } else if (c < 160) {
        int cc = c - 64;
        int d = cc % 3;
        int mI = cc / 3;
        float mu = g_stats[g][3 + d] / (cntf * 32.0f);
        a = weight[64 + mI];
        b = -mu * a;
    } else {
        int cc = c - 160;
        int d = cc % 5;
        int mI = cc / 5;
        float mu = g_stats[g][6 + d] / (cntf * 16.0f);
        a = weight[96 + mI];
        b = -mu * a;
    }
    g_A[idx] = a;
    g_B[idx] = b;
}

// ---------------------------------------------------------------------------
// Pass 2: streaming affine apply. 4 float4 per thread (ILP=4), blocks process
// x in REVERSE macro-order so the tail of x (still hot in L2 from the stats
// pass) is consumed first. Also re-zeros g_stats for the next graph replay.
// ---------------------------------------------------------------------------
#define APPLY_ITER 4
__global__ __launch_bounds__(256) void apply_kernel(const float* __restrict__ x,
                                                    const int* __restrict__ batch,
                                                    float* __restrict__ out,
                                                    int n_nodes) {
    const int total = n_nodes * NFLOAT4;
    const int rb = gridDim.x - 1 - blockIdx.x;        // reversed block order
    const int base = rb * (256 * APPLY_ITER) + threadIdx.x;

#pragma unroll
    for (int k = 0; k < APPLY_ITER; k++) {
        int idx = base + k * 256;
        if (idx < total) {
            int n = idx / NFLOAT4;
            int c4 = idx - n * NFLOAT4;
            int g = __ldg(&batch[n]);

            float4 xv = __ldg(&((const float4*)x)[idx]);
            float4 av = ((const float4*)g_A)[g * NFLOAT4 + c4];
            float4 bv = ((const float4*)g_B)[g * NFLOAT4 + c4];

            float4 ov;
            ov.x = fmaf(xv.x, av.x, bv.x);
            ov.y = fmaf(xv.y, av.y, bv.y);
            ov.z = fmaf(xv.z, av.z, bv.z);
            ov.w = fmaf(xv.w, av.w, bv.w);
            ((float4*)out)[idx] = ov;
        }
    }

    // epilogue: re-zero stats for the next replay (module-load state is zero,
    // and every run leaves it zero -> deterministic across graph replays)
    if (blockIdx.x == 0 && threadIdx.x < 256) {
        for (int i = threadIdx.x; i < N_GRAPHS * 12; i += 256)
            ((float*)g_stats)[i] = 0.0f;
    }
}

extern "C" void kernel_launch(void* const* d_in, const int* in_sizes, int n_in,
                              void* d_out, int out_size) {
    const float* x = (const float*)d_in[0];
    const int* batch = (const int*)d_in[1];
    const float* weight = (const float*)d_in[2];
    const float* bias = (const float*)d_in[3];
    float* out = (float*)d_out;

    int n_nodes = in_sizes[1];

    stats_kernel<<<STATS_GRID, 256>>>(x, batch, n_nodes);

    int np = N_GRAPHS * DIMTOT;
    params_kernel<<<(np + 255) / 256, 256>>>(weight, bias);

    int total = n_nodes * NFLOAT4;
    int blocks2 = (total + 256 * APPLY_ITER - 1) / (256 * APPLY_ITER);
    apply_kernel<<<blocks2, 256>>>(x, batch, out, n_nodes);
}

// round 15
// speedup vs baseline: 1.2779x; 1.2779x over previous
#include <cuda_runtime.h>
#include <cuda_bf16.h>

#define N_GRAPHS 64
#define DIMTOT   240     // 64*1 + 32*3 + 16*5
#define NFLOAT4  60      // DIMTOT/4
#define EPS      1e-05f
#define STATS_GRID 1184  // 148 SMs * 8 blocks (32 regs, 256 thr) = ONE full wave

// stats layout per graph: [0]=count, [1]=s0, [2]=ss0, [3..5]=s1[d], [6..10]=s2[d]
__device__ float g_stats[N_GRAPHS][12];   // zero at load; re-zeroed by apply epilogue
__device__ float g_A[N_GRAPHS * DIMTOT];
__device__ float g_B[N_GRAPHS * DIMTOT];

// ---------------------------------------------------------------------------
// Pass 1 (column-striped, R9/R13 structure — measured best):
// block b owns nodes [bN/B,(b+1)N/B). Warp k owns columns [32k,32k+32)
// (warp 7: cols 224..239, lanes 0..15). Each lane has ONE fixed column ->
// one accumulator, fixed stat bucket, no routing in hot loop.
// 8-node chunks with a single batch check; flush only at graph boundaries.
// Grid = exactly one resident wave (148*8 blocks @ 32 regs) -> no tail wave.
// ---------------------------------------------------------------------------
__global__ __launch_bounds__(256) void stats_kernel(const float* __restrict__ x,
                                                    const int* __restrict__ batch,
                                                    int n_nodes) {
    const int b = blockIdx.x;
    const int warp = threadIdx.x >> 5;
    const int lane = threadIdx.x & 31;
    const int n0 = (int)((long long)b * n_nodes / STATS_GRID);
    const int n1 = (int)((long long)(b + 1) * n_nodes / STATS_GRID);
    if (n0 >= n1) return;

    const int c = (warp < 7) ? warp * 32 + lane : 224 + lane;
    const bool active = (warp < 7) || (lane < 16);
    const bool isA = (warp < 2);
    int bkt;
    if (c < 64)        bkt = 1;
    else if (c < 160)  bkt = 3 + (c - 64) % 3;
    else               bkt = 6 + (c - 160) % 5;

    float acc = 0.0f, asq = 0.0f;
    int seg_start = n0;
    int cur_g = __ldg(&batch[n0]);

    auto flush = [&](int g, int cnt) {
        if (isA) {
            float v0 = acc, v1 = asq;
#pragma unroll
            for (int off = 16; off > 0; off >>= 1) {
                v0 += __shfl_xor_sync(0xFFFFFFFFu, v0, off);
                v1 += __shfl_xor_sync(0xFFFFFFFFu, v1, off);
            }
            if (lane == 0) {
                atomicAdd(&g_stats[g][1], v0);
                atomicAdd(&g_stats[g][2], v1);
                if (warp == 0) atomicAdd(&g_stats[g][0], (float)cnt);
            }
        } else if (warp < 5) {
            float v[3];
#pragma unroll
            for (int d = 0; d < 3; d++) v[d] = (bkt == 3 + d) ? acc : 0.0f;
#pragma unroll
            for (int off = 16; off > 0; off >>= 1)
#pragma unroll
                for (int d = 0; d < 3; d++)
                    v[d] += __shfl_xor_sync(0xFFFFFFFFu, v[d], off);
            if (lane == 0)
#pragma unroll
                for (int d = 0; d < 3; d++)
                    atomicAdd(&g_stats[g][3 + d], v[d]);
        } else {
            float v[5];
#pragma unroll
            for (int d = 0; d < 5; d++) v[d] = (active && bkt == 6 + d) ? acc : 0.0f;
#pragma unroll
            for (int off = 16; off > 0; off >>= 1)
#pragma unroll
                for (int d = 0; d < 5; d++)
                    v[d] += __shfl_xor_sync(0xFFFFFFFFu, v[d], off);
            if (lane == 0)
#pragma unroll
                for (int d = 0; d < 5; d++)
                    atomicAdd(&g_stats[g][6 + d], v[d]);
        }
    };

    int n = n0;
    while (n < n1) {
        int chunk = min(8, n1 - n);
        int gend = __ldg(&batch[n + chunk - 1]);
        if (gend == cur_g) {
            if (chunk == 8) {
                float t[8];
#pragma unroll
                for (int u = 0; u < 8; u++)
                    t[u] = active ? __ldg(x + (size_t)(n + u) * DIMTOT + c) : 0.0f;
#pragma unroll
                for (int u = 0; u < 8; u++) {
                    acc += t[u];
                    if (isA) asq += t[u] * t[u];
                }
            } else {
                for (int u = 0; u < chunk; u++) {
                    float v = active ? __ldg(x + (size_t)(n + u) * DIMTOT + c) : 0.0f;
                    acc += v;
                    if (isA) asq += v * v;
                }
            }
            n += chunk;
        } else {
            // boundary inside chunk: per-node path
            int g = __ldg(&batch[n]);
            if (g != cur_g) {
                flush(cur_g, n - seg_start);
                seg_start = n;
                cur_g = g;
                acc = 0.0f;
                asq = 0.0f;
            }
            float v = active ? __ldg(x + (size_t)n * DIMTOT + c) : 0.0f;
            acc += v;
            if (isA) asq += v * v;
            n++;
        }
    }
    flush(cur_g, n - seg_start);
}

// ---------------------------------------------------------------------------
// Pass 1.5: build per-(graph,column) affine params  out = x*A + B
// ---------------------------------------------------------------------------
__global__ void params_kernel(const float* __restrict__ weight,
                              const float* __restrict__ bias) {
    int idx = blockIdx.x * blockDim.x + threadIdx.x;
    if (idx >= N_GRAPHS * DIMTOT) return;
    int g = idx / DIMTOT;
    int c = idx - g * DIMTOT;

    float cntf = fmaxf(g_stats[g][0], 1.0f);
    float a, b;
    if (c < 64) {
        float inv64 = 1.0f / (cntf * 64.0f);
        float m = g_stats[g][1] * inv64;
        float var = g_stats[g][2] * inv64 - m * m;
        float inv = 1.0f / (sqrtf(fmaxf(var, 0.0f)) + EPS);
        a = weight[c] * inv;
        b = bias[c] - m * a;
    } else if (c < 160) {
        int cc = c - 64;
        int d = cc % 3;
        int mI = cc / 3;
        float mu = g_stats[g][3 + d] / (cntf * 32.0f);
        a = weight[64 + mI];
        b = -mu * a;
    } else {
        int cc = c - 160;
        int d = cc % 5;
        int mI = cc / 5;
        float mu = g_stats[g][6 + d] / (cntf * 16.0f);
        a = weight[96 + mI];
        b = -mu * a;
    }
    g_A[idx] = a;
    g_B[idx] = b;
}

// ---------------------------------------------------------------------------
// Pass 2: streaming affine apply. 4 float4 per thread (ILP=4), blocks process
// x in REVERSE macro-order so the tail of x (still hot in L2 from the stats
// pass) is consumed first. Also re-zeros g_stats for the next graph replay.
// ---------------------------------------------------------------------------
#define APPLY_ITER 4
__global__ __launch_bounds__(256) void apply_kernel(const float* __restrict__ x,
                                                    const int* __restrict__ batch,
                                                    float* __restrict__ out,
                                                    int n_nodes) {
    const int total = n_nodes * NFLOAT4;
    const int rb = gridDim.x - 1 - blockIdx.x;        // reversed block order
    const int base = rb * (256 * APPLY_ITER) + threadIdx.x;

#pragma unroll
    for (int k = 0; k < APPLY_ITER; k++) {
        int idx = base + k * 256;
        if (idx < total) {
            int n = idx / NFLOAT4;
            int c4 = idx - n * NFLOAT4;
            int g = __ldg(&batch[n]);

            float4 xv = __ldg(&((const float4*)x)[idx]);
            float4 av = ((const float4*)g_A)[g * NFLOAT4 + c4];
            float4 bv = ((const float4*)g_B)[g * NFLOAT4 + c4];

            float4 ov;
            ov.x = fmaf(xv.x, av.x, bv.x);
            ov.y = fmaf(xv.y, av.y, bv.y);
            ov.z = fmaf(xv.z, av.z, bv.z);
            ov.w = fmaf(xv.w, av.w, bv.w);
            ((float4*)out)[idx] = ov;
        }
    }

    // epilogue: re-zero stats for the next replay (module-load state is zero,
    // and every run leaves it zero -> deterministic across graph replays)
    if (blockIdx.x == 0 && threadIdx.x < 256) {
        for (int i = threadIdx.x; i < N_GRAPHS * 12; i += 256)
            ((float*)g_stats)[i] = 0.0f;
    }
}

extern "C" void kernel_launch(void* const* d_in, const int* in_sizes, int n_in,
                              void* d_out, int out_size) {
    const float* x = (const float*)d_in[0];
    const int* batch = (const int*)d_in[1];
    const float* weight = (const float*)d_in[2];
    const float* bias = (const float*)d_in[3];
    float* out = (float*)d_out;

    int n_nodes = in_sizes[1];

    stats_kernel<<<STATS_GRID, 256>>>(x, batch, n_nodes);

    int np = N_GRAPHS * DIMTOT;
    params_kernel<<<(np + 255) / 256, 256>>>(weight, bias);

    int total = n_nodes * NFLOAT4;
    int blocks2 = (total + 256 * APPLY_ITER - 1) / (256 * APPLY_ITER);
    apply_kernel<<<blocks2, 256>>>(x, batch, out, n_nodes);
}